// round 5
// baseline (speedup 1.0000x reference)
#include <cuda_runtime.h>
#include <cuda_fp16.h>
#include <cstdint>

#define E_  64
#define KT_ 4
#define H_  2048
#define I_  1536
#define GS_ 128
#define T_  1024
#define C_  128
#define A_  (T_*KT_)

// ---------------- static scratch ----------------
__device__ __align__(16) __half d_xh[T_*H_];        // x in fp16
__device__ __align__(16) __half d_hbuf[E_*C_*I_];   // expert SwiGLU intermediate (fp16)
__device__ __align__(16) __half d_shh[T_*I_];       // shared-expert intermediate (fp16)
__device__ int   d_topk_idx[A_];
__device__ float d_topk_w[A_];
__device__ int   d_slot_tok[E_*C_];
__device__ float d_slot_w[E_*C_];
__device__ int   d_nrows[E_];

__constant__ float c_lut[16] = {0.0f, 0.5f, 1.0f, 1.5f, 2.0f, 3.0f, 4.0f, 6.0f,
                                -0.0f,-0.5f,-1.0f,-1.5f,-2.0f,-3.0f,-4.0f,-6.0f};

// ---------------- helpers ----------------
__device__ __forceinline__ uint32_t smem_u32(const void* p) {
    uint32_t a;
    asm("{ .reg .u64 t; cvta.to.shared.u64 t, %1; cvt.u32.u64 %0, t; }" : "=r"(a) : "l"(p));
    return a;
}
__device__ __forceinline__ void cp16(uint32_t dst, const void* src, bool pred) {
    int sz = pred ? 16 : 0;
    asm volatile("cp.async.ca.shared.global [%0], [%1], 16, %2;"
        :: "r"(dst), "l"(src), "r"(sz) : "memory");
}
#define CP_COMMIT() asm volatile("cp.async.commit_group;" ::: "memory")
#define CP_WAIT1()  asm volatile("cp.async.wait_group 1;" ::: "memory")

__device__ __forceinline__ void ldsm_x4(uint32_t addr, uint32_t r[4]) {
    asm volatile("ldmatrix.sync.aligned.m8n8.x4.shared.b16 {%0,%1,%2,%3}, [%4];"
        : "=r"(r[0]), "=r"(r[1]), "=r"(r[2]), "=r"(r[3]) : "r"(addr));
}
__device__ __forceinline__ void ldsm_x2(uint32_t addr, uint32_t r[2]) {
    asm volatile("ldmatrix.sync.aligned.m8n8.x2.shared.b16 {%0,%1}, [%2];"
        : "=r"(r[0]), "=r"(r[1]) : "r"(addr));
}
__device__ __forceinline__ void mma16816(float c[4], const uint32_t a[4], const uint32_t b[2]) {
    asm volatile("mma.sync.aligned.m16n8k16.row.col.f32.f16.f16.f32 "
        "{%0,%1,%2,%3}, {%4,%5,%6,%7}, {%8,%9}, {%0,%1,%2,%3};"
        : "+f"(c[0]), "+f"(c[1]), "+f"(c[2]), "+f"(c[3])
        : "r"(a[0]), "r"(a[1]), "r"(a[2]), "r"(a[3]), "r"(b[0]), "r"(b[1]));
}
__device__ __forceinline__ uint4 dq_word(uint32_t w, const uint32_t* lut, __half2 s2) {
    __half2 q0 = __hmul2(*(const __half2*)&lut[w & 255], s2);
    __half2 q1 = __hmul2(*(const __half2*)&lut[(w >> 8) & 255], s2);
    __half2 q2 = __hmul2(*(const __half2*)&lut[(w >> 16) & 255], s2);
    __half2 q3 = __hmul2(*(const __half2*)&lut[w >> 24], s2);
    uint4 o;
    o.x = *(uint32_t*)&q0; o.y = *(uint32_t*)&q1;
    o.z = *(uint32_t*)&q2; o.w = *(uint32_t*)&q3;
    return o;
}

// smem geometry: rows of 64 halfs + 8 pad = 144 bytes
#define ROWB 144
#define ABUF (64*ROWB)            // 9216  (A: 64 rows)
#define BBUF (128*ROWB)           // 18432 (B: 128 rows)
// gemm1 layout
#define G1_XA   1024
#define G1_BG   (G1_XA + 2*ABUF)        // 19456
#define G1_BU   (G1_BG + 2*BBUF)        // 56320
#define G1_SG   (G1_BU + 2*BBUF)        // 93184 (staging gate: 2 x 4096)
#define G1_SU   (G1_SG + 8192)          // 101376
#define SM1_TOTAL (G1_SU + 8192)        // 109568
// gemm2 layout
#define G2_XA   1024
#define G2_B    (G2_XA + 2*ABUF)        // 19456
#define G2_S    (G2_B + 2*BBUF)         // 56320
#define SM2_TOTAL (G2_S + 8192)         // 64512

// ---------------- x -> fp16 ----------------
__global__ void cvt_x_kernel(const float* __restrict__ x) {
    int i = (blockIdx.x * 256 + threadIdx.x) * 8;
    float4 a = *(const float4*)(x + i);
    float4 b = *(const float4*)(x + i + 4);
    __half2 h0 = __floats2half2_rn(a.x, a.y), h1 = __floats2half2_rn(a.z, a.w);
    __half2 h2 = __floats2half2_rn(b.x, b.y), h3 = __floats2half2_rn(b.z, b.w);
    uint4 o;
    o.x = *(uint32_t*)&h0; o.y = *(uint32_t*)&h1;
    o.z = *(uint32_t*)&h2; o.w = *(uint32_t*)&h3;
    *(uint4*)(d_xh + i) = o;
}

// ---------------- routing ----------------
__global__ void routing_kernel(const float* __restrict__ x,
                               const float* __restrict__ gw) {
    int t = blockIdx.x;
    __shared__ float xs[H_];
    __shared__ float logits[E_];
    int tid = threadIdx.x;
    for (int i = tid; i < H_; i += 256) xs[i] = x[t*H_ + i];
    __syncthreads();
    int warp = tid >> 5, lane = tid & 31;
    for (int e = warp; e < E_; e += 8) {
        const float* w = gw + e*H_;
        float s = 0.f;
        for (int h = lane; h < H_; h += 32) s += xs[h] * w[h];
        #pragma unroll
        for (int o = 16; o; o >>= 1) s += __shfl_down_sync(0xffffffffu, s, o);
        if (lane == 0) logits[e] = s;
    }
    __syncthreads();
    if (tid == 0) {
        int   idx[KT_];
        float val[KT_];
        #pragma unroll
        for (int k = 0; k < KT_; k++) {
            float best = -1e38f; int bi = 0;
            for (int e = 0; e < E_; e++)
                if (logits[e] > best) { best = logits[e]; bi = e; }
            idx[k] = bi; val[k] = best; logits[bi] = -1e38f;
        }
        float m = val[0], sum = 0.f, w[KT_];
        #pragma unroll
        for (int k = 0; k < KT_; k++) { w[k] = expf(val[k] - m); sum += w[k]; }
        #pragma unroll
        for (int k = 0; k < KT_; k++) {
            d_topk_idx[t*KT_ + k] = idx[k];
            d_topk_w  [t*KT_ + k] = w[k] / sum;
        }
    }
}

// ---------------- dispatch ----------------
__global__ void dispatch_kernel() {
    int e = blockIdx.x;
    int tid = threadIdx.x;
    int lane = tid & 31, warp = tid >> 5;
    __shared__ int warp_cnt[8];
    __shared__ int running_s;
    if (tid == 0) running_s = 0;
    __syncthreads();
    for (int base = 0; base < A_; base += 256) {
        int a = base + tid;
        int match = (d_topk_idx[a] == e) ? 1 : 0;
        unsigned bal = __ballot_sync(0xffffffffu, match);
        if (lane == 0) warp_cnt[warp] = __popc(bal);
        __syncthreads();
        int off = running_s;
        for (int wn = 0; wn < warp; wn++) off += warp_cnt[wn];
        int pos = off + __popc(bal & ((1u << lane) - 1));
        if (match && pos < C_) {
            d_slot_tok[e*C_ + pos] = a >> 2;
            d_slot_w  [e*C_ + pos] = d_topk_w[a];
        }
        __syncthreads();
        if (tid == 0) {
            int tot = 0;
            #pragma unroll
            for (int wn = 0; wn < 8; wn++) tot += warp_cnt[wn];
            running_s += tot;
        }
        __syncthreads();
    }
    if (tid == 0) d_nrows[e] = min(running_s, C_);
}

// ---------------- GEMM1 (gate+up + SwiGLU), BM=64, cp.async pipeline ----------------
template<bool SHARED>
__global__ void __launch_bounds__(256, 1)
hmma_gemm1(const int* __restrict__ gp, const float* __restrict__ gs,
           const int* __restrict__ up, const float* __restrict__ us)
{
    extern __shared__ char smem[];
    const int e     = SHARED ? 0 : blockIdx.z;
    const int nrows = SHARED ? T_ : d_nrows[e];
    const int m0    = blockIdx.y * 64;
    if (m0 >= nrows) return;
    const int n0 = blockIdx.x * 128;
    const int tid = threadIdx.x, wid = tid >> 5, lane = tid & 31;
    const uint32_t sb = smem_u32(smem);
    uint32_t* lut = (uint32_t*)smem;

    const int*   gpk = gp + (size_t)(SHARED ? 0 : e) * (I_*(H_/8));
    const int*   upk = up + (size_t)(SHARED ? 0 : e) * (I_*(H_/8));
    const float* gsc = gs + (size_t)(SHARED ? 0 : e) * ((H_/GS_)*I_);
    const float* usc = us + (size_t)(SHARED ? 0 : e) * ((H_/GS_)*I_);
    __half* outb = SHARED ? d_shh : d_hbuf + (size_t)e * C_ * I_;

    {
        __half lo = __float2half_rn(c_lut[tid & 15]);
        __half hi = __float2half_rn(c_lut[tid >> 4]);
        lut[tid] = (uint32_t)__half_as_ushort(lo) | ((uint32_t)__half_as_ushort(hi) << 16);
    }

    // fill roles
    const int arow = tid >> 2, aseg = tid & 3;           // A: 64 rows, 4 thr/row, 2x16B each
    int atok;
    if (SHARED) atok = m0 + arow;
    else        atok = (arow < nrows - m0) ? d_slot_tok[e*C_ + m0 + arow] : -1;
    const int brow = tid >> 1, bhalf = tid & 1;          // B: 128 rows, 2 thr/row, 1x16B each
    const int og = n0 + brow;

    // compute roles: 8 warps = 2 (M) x 4 (N); warp tile 32 tok x 32 out
    const int wm = wid & 1, wn = wid >> 1;
    const uint32_t a_lane = sb + G1_XA + (uint32_t)((wm*32 + (lane & 15))*ROWB + (lane >> 4)*16);
    const uint32_t b_off  = (uint32_t)((wn*32 + (lane & 7))*ROWB + ((lane >> 3) & 1)*16);

    float accg[2][4][4], accu[2][4][4];
    #pragma unroll
    for (int mt = 0; mt < 2; mt++)
        #pragma unroll
        for (int nt = 0; nt < 4; nt++)
            #pragma unroll
            for (int q = 0; q < 4; q++) { accg[mt][nt][q] = 0.f; accu[mt][nt][q] = 0.f; }

    float sgv[2], suv[2];
    const int NC = H_ / 64;

    // issue copies for chunk c into buffer c&1
    auto issue = [&](int c) {
        const int p = c & 1;
        // A: 2 x 16B per thread
        {
            uint32_t dst = sb + G1_XA + p*ABUF + (uint32_t)(arow*ROWB + aseg*32);
            const char* src = (const char*)(d_xh + (size_t)(atok < 0 ? 0 : atok)*H_ + c*64 + aseg*16);
            cp16(dst,      src,      atok >= 0);
            cp16(dst + 16, src + 16, atok >= 0);
        }
        // B packed staging: 1 x 16B per matrix per thread
        {
            uint32_t dg = sb + G1_SG + p*4096 + (uint32_t)(brow*32 + bhalf*16);
            uint32_t du = sb + G1_SU + p*4096 + (uint32_t)(brow*32 + bhalf*16);
            cp16(dg, gpk + og*(H_/8) + c*8 + bhalf*4, true);
            cp16(du, upk + og*(H_/8) + c*8 + bhalf*4, true);
        }
        sgv[p] = gsc[(c >> 1)*I_ + og];
        suv[p] = usc[(c >> 1)*I_ + og];
    };

    issue(0); CP_COMMIT();
    issue(1); CP_COMMIT();
    __syncthreads();   // LUT visible

    for (int c = 0; c < NC; c++) {
        const int p = c & 1;
        CP_WAIT1();    // group c landed
        // dequant own staged words -> STS B tiles
        {
            uint4 gw4 = *(const uint4*)(smem + G1_SG + p*4096 + brow*32 + bhalf*16);
            uint4 uw4 = *(const uint4*)(smem + G1_SU + p*4096 + brow*32 + bhalf*16);
            __half2 sg2 = __half2half2(__float2half_rn(sgv[p]));
            __half2 su2 = __half2half2(__float2half_rn(suv[p]));
            uint32_t gw_[4] = {gw4.x, gw4.y, gw4.z, gw4.w};
            uint32_t uw_[4] = {uw4.x, uw4.y, uw4.z, uw4.w};
            char* gb = smem + G1_BG + p*BBUF;
            char* ub = smem + G1_BU + p*BBUF;
            #pragma unroll
            for (int j = 0; j < 4; j++) {
                *(uint4*)(gb + brow*ROWB + (bhalf*4 + j)*16) = dq_word(gw_[j], lut, sg2);
                *(uint4*)(ub + brow*ROWB + (bhalf*4 + j)*16) = dq_word(uw_[j], lut, su2);
            }
        }
        __syncthreads();   // buffer p fully visible (A cp.async + B STS)
        // compute
        {
            const uint32_t ab  = a_lane + p*ABUF;
            const uint32_t gbl = sb + G1_BG + p*BBUF + b_off;
            const uint32_t ubl = sb + G1_BU + p*BBUF + b_off;
            #pragma unroll
            for (int ks = 0; ks < 4; ks++) {
                uint32_t af[2][4];
                ldsm_x4(ab + 0*16*ROWB + ks*32, af[0]);
                ldsm_x4(ab + 1*16*ROWB + ks*32, af[1]);
                #pragma unroll
                for (int nt = 0; nt < 4; nt++) {
                    uint32_t bgf[2], buf_[2];
                    ldsm_x2(gbl + nt*8*ROWB + ks*32, bgf);
                    ldsm_x2(ubl + nt*8*ROWB + ks*32, buf_);
                    mma16816(accg[0][nt], af[0], bgf);
                    mma16816(accg[1][nt], af[1], bgf);
                    mma16816(accu[0][nt], af[0], buf_);
                    mma16816(accu[1][nt], af[1], buf_);
                }
            }
        }
        __syncthreads();   // done reading buffer p
        if (c + 2 < NC) issue(c + 2);
        CP_COMMIT();       // always commit to keep group accounting uniform
    }

    // SwiGLU epilogue
    const int r0 = wm*32 + (lane >> 2);
    const int c0 = (lane & 3)*2;
    #pragma unroll
    for (int mt = 0; mt < 2; mt++) {
        #pragma unroll
        for (int nt = 0; nt < 4; nt++) {
            int rowA = r0 + mt*16, rowB = rowA + 8;
            int col = n0 + wn*32 + nt*8 + c0;
            float g0 = accg[mt][nt][0], g1 = accg[mt][nt][1];
            float u0 = accu[mt][nt][0], u1 = accu[mt][nt][1];
            float g2 = accg[mt][nt][2], g3 = accg[mt][nt][3];
            float u2 = accu[mt][nt][2], u3 = accu[mt][nt][3];
            float h0 = g0*u0/(1.f+__expf(-g0)), h1 = g1*u1/(1.f+__expf(-g1));
            float h2 = g2*u2/(1.f+__expf(-g2)), h3 = g3*u3/(1.f+__expf(-g3));
            __half2 p01 = __floats2half2_rn(h0, h1);
            __half2 p23 = __floats2half2_rn(h2, h3);
            *(uint32_t*)(outb + (size_t)(m0 + rowA)*I_ + col) = *(uint32_t*)&p01;
            *(uint32_t*)(outb + (size_t)(m0 + rowB)*I_ + col) = *(uint32_t*)&p23;
        }
    }
}

// ---------------- GEMM2 (down + weighted combine), BM=64, cp.async pipeline ----------------
template<bool SHARED>
__global__ void __launch_bounds__(256, 1)
hmma_gemm2(const int* __restrict__ dp, const float* __restrict__ ds,
           float* __restrict__ y)
{
    extern __shared__ char smem[];
    const int e     = SHARED ? 0 : blockIdx.z;
    const int nrows = SHARED ? T_ : d_nrows[e];
    const int m0    = blockIdx.y * 64;
    if (m0 >= nrows) return;
    const int n0 = blockIdx.x * 128;
    const int tid = threadIdx.x, wid = tid >> 5, lane = tid & 31;
    const uint32_t sb = smem_u32(smem);
    uint32_t* lut = (uint32_t*)smem;

    const int*   dpk = dp + (size_t)(SHARED ? 0 : e) * (H_*(I_/8));
    const float* dsc = ds + (size_t)(SHARED ? 0 : e) * ((I_/GS_)*H_);
    const __half* hb = SHARED ? d_shh : d_hbuf + (size_t)e * C_ * I_;

    {
        __half lo = __float2half_rn(c_lut[tid & 15]);
        __half hi = __float2half_rn(c_lut[tid >> 4]);
        lut[tid] = (uint32_t)__half_as_ushort(lo) | ((uint32_t)__half_as_ushort(hi) << 16);
    }

    const int arow = tid >> 2, aseg = tid & 3;
    const int brow = tid >> 1, bhalf = tid & 1;
    const int og = n0 + brow;

    const int wm = wid & 1, wn = wid >> 1;
    const uint32_t a_lane = sb + G2_XA + (uint32_t)((wm*32 + (lane & 15))*ROWB + (lane >> 4)*16);
    const uint32_t b_off  = (uint32_t)((wn*32 + (lane & 7))*ROWB + ((lane >> 3) & 1)*16);

    float acc[2][4][4];
    #pragma unroll
    for (int mt = 0; mt < 2; mt++)
        #pragma unroll
        for (int nt = 0; nt < 4; nt++)
            #pragma unroll
            for (int q = 0; q < 4; q++) acc[mt][nt][q] = 0.f;

    float dsv[2];
    const int NC = I_ / 64;

    auto issue = [&](int c) {
        const int p = c & 1;
        {
            uint32_t dst = sb + G2_XA + p*ABUF + (uint32_t)(arow*ROWB + aseg*32);
            const char* src = (const char*)(hb + (size_t)(m0 + arow)*I_ + c*64 + aseg*16);
            cp16(dst,      src,      true);
            cp16(dst + 16, src + 16, true);
        }
        {
            uint32_t dg = sb + G2_S + p*4096 + (uint32_t)(brow*32 + bhalf*16);
            cp16(dg, dpk + og*(I_/8) + c*8 + bhalf*4, true);
        }
        dsv[p] = dsc[(c >> 1)*H_ + og];
    };

    issue(0); CP_COMMIT();
    issue(1); CP_COMMIT();
    __syncthreads();

    for (int c = 0; c < NC; c++) {
        const int p = c & 1;
        CP_WAIT1();
        {
            uint4 dw4 = *(const uint4*)(smem + G2_S + p*4096 + brow*32 + bhalf*16);
            __half2 s2 = __half2half2(__float2half_rn(dsv[p]));
            uint32_t dw_[4] = {dw4.x, dw4.y, dw4.z, dw4.w};
            char* bb = smem + G2_B + p*BBUF;
            #pragma unroll
            for (int j = 0; j < 4; j++)
                *(uint4*)(bb + brow*ROWB + (bhalf*4 + j)*16) = dq_word(dw_[j], lut, s2);
        }
        __syncthreads();
        {
            const uint32_t ab = a_lane + p*ABUF;
            const uint32_t bb = sb + G2_B + p*BBUF + b_off;
            #pragma unroll
            for (int ks = 0; ks < 4; ks++) {
                uint32_t af[2][4];
                ldsm_x4(ab + 0*16*ROWB + ks*32, af[0]);
                ldsm_x4(ab + 1*16*ROWB + ks*32, af[1]);
                #pragma unroll
                for (int nt = 0; nt < 4; nt++) {
                    uint32_t bf[2];
                    ldsm_x2(bb + nt*8*ROWB + ks*32, bf);
                    mma16816(acc[0][nt], af[0], bf);
                    mma16816(acc[1][nt], af[1], bf);
                }
            }
        }
        __syncthreads();
        if (c + 2 < NC) issue(c + 2);
        CP_COMMIT();
    }

    // combine epilogue
    const int r0 = wm*32 + (lane >> 2);
    const int c0 = (lane & 3)*2;
    #pragma unroll
    for (int mt = 0; mt < 2; mt++) {
        int rowA = r0 + mt*16, rowB = rowA + 8;
        int tokA = -1, tokB = -1; float wA = 0.f, wB = 0.f;
        if (SHARED) { tokA = m0 + rowA; tokB = m0 + rowB; wA = wB = 1.f; }
        else {
            if (m0 + rowA < nrows) { tokA = d_slot_tok[e*C_ + m0 + rowA]; wA = d_slot_w[e*C_ + m0 + rowA]; }
            if (m0 + rowB < nrows) { tokB = d_slot_tok[e*C_ + m0 + rowB]; wB = d_slot_w[e*C_ + m0 + rowB]; }
        }
        #pragma unroll
        for (int nt = 0; nt < 4; nt++) {
            int col = n0 + wn*32 + nt*8 + c0;
            if (tokA >= 0) {
                atomicAdd(y + (size_t)tokA*H_ + col,     acc[mt][nt][0]*wA);
                atomicAdd(y + (size_t)tokA*H_ + col + 1, acc[mt][nt][1]*wA);
            }
            if (tokB >= 0) {
                atomicAdd(y + (size_t)tokB*H_ + col,     acc[mt][nt][2]*wB);
                atomicAdd(y + (size_t)tokB*H_ + col + 1, acc[mt][nt][3]*wB);
            }
        }
    }
}

// ---------------- launch ----------------
extern "C" void kernel_launch(void* const* d_in, const int* in_sizes, int n_in,
                              void* d_out, int out_size) {
    (void)in_sizes; (void)n_in; (void)out_size;
    const float* x    = (const float*)d_in[0];
    const float* gw   = (const float*)d_in[1];
    const float* gsc  = (const float*)d_in[2];
    const float* usc  = (const float*)d_in[3];
    const float* dsc  = (const float*)d_in[4];
    const float* sgsc = (const float*)d_in[5];
    const float* susc = (const float*)d_in[6];
    const float* sdsc = (const float*)d_in[7];
    const int*   gpk  = (const int*)d_in[8];
    const int*   upk  = (const int*)d_in[9];
    const int*   dpk  = (const int*)d_in[10];
    const int*   sgpk = (const int*)d_in[11];
    const int*   supk = (const int*)d_in[12];
    const int*   sdpk = (const int*)d_in[13];
    float* y = (float*)d_out;

    cudaFuncSetAttribute(hmma_gemm1<false>, cudaFuncAttributeMaxDynamicSharedMemorySize, SM1_TOTAL);
    cudaFuncSetAttribute(hmma_gemm1<true>,  cudaFuncAttributeMaxDynamicSharedMemorySize, SM1_TOTAL);
    cudaFuncSetAttribute(hmma_gemm2<false>, cudaFuncAttributeMaxDynamicSharedMemorySize, SM2_TOTAL);
    cudaFuncSetAttribute(hmma_gemm2<true>,  cudaFuncAttributeMaxDynamicSharedMemorySize, SM2_TOTAL);

    cudaMemsetAsync(y, 0, (size_t)T_ * H_ * sizeof(float), 0);
    cvt_x_kernel<<<(T_*H_)/2048, 256>>>(x);
    routing_kernel<<<T_, 256>>>(x, gw);
    dispatch_kernel<<<E_, 256>>>();

    { dim3 g(I_/128, 2, E_);     hmma_gemm1<false><<<g, 256, SM1_TOTAL>>>(gpk, gsc, upk, usc); }
    { dim3 g(I_/128, T_/64, 1);  hmma_gemm1<true><<<g, 256, SM1_TOTAL>>>(sgpk, sgsc, supk, susc); }
    { dim3 g(H_/128, 2, E_);     hmma_gemm2<false><<<g, 256, SM2_TOTAL>>>(dpk, dsc, y); }
    { dim3 g(H_/128, T_/64, 1);  hmma_gemm2<true><<<g, 256, SM2_TOTAL>>>(sdpk, sdsc, y); }
}